// round 5
// baseline (speedup 1.0000x reference)
#include <cuda_runtime.h>
#include <math.h>
#include <stdint.h>

#define Bq 64
#define Sq 128
#define Eq 512
#define Hq 1024
#define Vq 50257
#define KIq (Eq + Hq)   /* 1536 */
#define G4q (4 * Hq)    /* 4096 */
#define SBq (Sq * Bq)   /* 8192 */
#define NSLOT 16

// ---------------- scratch (static device globals; no runtime allocation) ----
__device__ float g_hW[Bq * Hq];
__device__ float g_spart[NSLOT * SBq];  // score column-partials per (s,b) row
__device__ float g_ctx[Bq * Hq];
__device__ float g_x[Bq * KIq];
__device__ float g_gates[Bq * G4q];

// ---------------- tf32 helpers ---------------------------------------------
__device__ __forceinline__ unsigned f2tf32(float x)
{
    unsigned r;
    asm("cvt.rna.tf32.f32 %0, %1;" : "=r"(r) : "f"(x));
    return r;
}
__device__ __forceinline__ void split_tf32(float x, unsigned& hi, unsigned& lo)
{
    hi = f2tf32(x);
    lo = f2tf32(x - __uint_as_float(hi));
}

__device__ __forceinline__ void mma_tf32r(float* c,
    unsigned a0, unsigned a1, unsigned a2, unsigned a3,
    unsigned b0, unsigned b1)
{
    asm volatile(
        "mma.sync.aligned.m16n8k8.row.col.f32.tf32.tf32.f32 "
        "{%0,%1,%2,%3}, {%4,%5,%6,%7}, {%8,%9}, {%0,%1,%2,%3};"
        : "+f"(c[0]), "+f"(c[1]), "+f"(c[2]), "+f"(c[3])
        : "r"(a0), "r"(a1), "r"(a2), "r"(a3), "r"(b0), "r"(b1));
}

__device__ __forceinline__ float tanh_fast(float x)
{
    float cx = fminf(fmaxf(x, -15.f), 15.f);
    float e = __expf(2.f * cx);
    return __fdividef(e - 1.f, e + 1.f);
}

// ================ fused 3xTF32 energy GEMM + score (legacy MMA) =============
// T = enc[8192,1024] @ U[1024,1024]^T (+Ub +hW), score partials out.
// BM=BN=128, BK=32, 256 threads, warp tile 32x64 (MI=2, NI=8).
// Smem tile layout: per row (128 rows), 4 k-groups of 8 k-values; within a
// group, k stored at slot p = 2*(k&3) + ((k>>2)&1) as uint2 {hi,lo}.
// A fragment (k=c, c+4; hi+lo) is then ONE uint4 at byte (lane&3)*16.
#define TROWB 320                       /* 256 data + 64 pad */
#define TTILEB (128 * TROWB)            /* 40960 */
#define TBUFB (2 * TTILEB)              /* A+B per buffer */
#define TSMEM (2 * TBUFB)               /* 163840 double buffered */

__global__ void __launch_bounds__(256)
tgemm_score_kernel(const float* __restrict__ enc, const float* __restrict__ U,
                   const float* __restrict__ Ub, const float* __restrict__ v)
{
    extern __shared__ char smem[];
    const int tid = threadIdx.x;
    const int lane = tid & 31;
    const int w = tid >> 5;
    const int lane4 = lane >> 2;        // row-within-8
    const int lanek = lane & 3;         // k-within-4
    const int warp_m = (w & 3) * 32;    // 4 warps along M
    const int warp_n = (w >> 2) * 64;   // 2 warps along N
    const int m0 = blockIdx.y * 128;
    const int n0 = blockIdx.x * 128;

    // loader assignment: each thread owns one row-half (16 k) of A and B
    const int lrow = tid >> 1;
    const int lkoff = (tid & 1) * 16;

    float4 pa[4], pb[4];
    float acc[2][8][4];
#pragma unroll
    for (int i = 0; i < 2; i++)
#pragma unroll
        for (int j = 0; j < 8; j++)
#pragma unroll
            for (int q = 0; q < 4; q++) acc[i][j][q] = 0.f;

    const float* Asrc = enc + (size_t)(m0 + lrow) * Hq + lkoff;
    const float* Bsrc = U + (size_t)(n0 + lrow) * Hq + lkoff;

    // prefetch chunk 0
#pragma unroll
    for (int u = 0; u < 4; u++) {
        pa[u] = *reinterpret_cast<const float4*>(Asrc + 4 * u);
        pb[u] = *reinterpret_cast<const float4*>(Bsrc + 4 * u);
    }

    for (int ch = 0; ch < 32; ch++) {
        char* bufA = smem + (ch & 1) * TBUFB;
        char* bufB = bufA + TTILEB;
        // ---- split + store prefetched regs into this chunk's buffer
#pragma unroll
        for (int u = 0; u < 4; u++) {
            int k = lkoff + 4 * u;
            int g = k >> 3;
            int odd = (k >> 2) & 1;
            int base = lrow * TROWB + g * 64 + odd * 8;
            uint2 t;
            split_tf32(pa[u].x, t.x, t.y);
            *reinterpret_cast<uint2*>(bufA + base) = t;
            split_tf32(pa[u].y, t.x, t.y);
            *reinterpret_cast<uint2*>(bufA + base + 16) = t;
            split_tf32(pa[u].z, t.x, t.y);
            *reinterpret_cast<uint2*>(bufA + base + 32) = t;
            split_tf32(pa[u].w, t.x, t.y);
            *reinterpret_cast<uint2*>(bufA + base + 48) = t;
            split_tf32(pb[u].x, t.x, t.y);
            *reinterpret_cast<uint2*>(bufB + base) = t;
            split_tf32(pb[u].y, t.x, t.y);
            *reinterpret_cast<uint2*>(bufB + base + 16) = t;
            split_tf32(pb[u].z, t.x, t.y);
            *reinterpret_cast<uint2*>(bufB + base + 32) = t;
            split_tf32(pb[u].w, t.x, t.y);
            *reinterpret_cast<uint2*>(bufB + base + 48) = t;
        }
        // ---- prefetch next chunk (latency hidden under MMA phase)
        if (ch + 1 < 32) {
            const float* An = Asrc + (ch + 1) * 32;
            const float* Bn = Bsrc + (ch + 1) * 32;
#pragma unroll
            for (int u = 0; u < 4; u++) {
                pa[u] = *reinterpret_cast<const float4*>(An + 4 * u);
                pb[u] = *reinterpret_cast<const float4*>(Bn + 4 * u);
            }
        }
        __syncthreads();

        // ---- MMA phase on this buffer
        const char* fa = bufA + (warp_m + lane4) * TROWB + lanek * 16;
        const char* fb = bufB + (warp_n + lane4) * TROWB + lanek * 16;
#pragma unroll
        for (int g = 0; g < 4; g++) {
            uint4 arl[2], arh[2];
#pragma unroll
            for (int i = 0; i < 2; i++) {
                arl[i] = *reinterpret_cast<const uint4*>(
                    fa + i * 16 * TROWB + g * 64);
                arh[i] = *reinterpret_cast<const uint4*>(
                    fa + (i * 16 + 8) * TROWB + g * 64);
            }
            uint4 bfr[8];
#pragma unroll
            for (int j = 0; j < 8; j++)
                bfr[j] = *reinterpret_cast<const uint4*>(
                    fb + j * 8 * TROWB + g * 64);
#pragma unroll
            for (int i = 0; i < 2; i++)
#pragma unroll
                for (int j = 0; j < 8; j++) {
                    // ah = hi frags, al = lo frags
                    mma_tf32r(acc[i][j], arl[i].x, arh[i].x, arl[i].z,
                              arh[i].z, bfr[j].y, bfr[j].w);        // Ah*Bl
                    mma_tf32r(acc[i][j], arl[i].y, arh[i].y, arl[i].w,
                              arh[i].w, bfr[j].x, bfr[j].z);        // Al*Bh
                    mma_tf32r(acc[i][j], arl[i].x, arh[i].x, arl[i].z,
                              arh[i].z, bfr[j].x, bfr[j].z);        // Ah*Bh
                }
        }
        __syncthreads();
    }

    // ---- fused epilogue: score partials over this warp's 64 columns -------
    float vv[8][2], uu[8][2];
#pragma unroll
    for (int j = 0; j < 8; j++)
#pragma unroll
        for (int qc = 0; qc < 2; qc++) {
            int c = n0 + warp_n + j * 8 + 2 * lanek + qc;
            vv[j][qc] = v[c];
            uu[j][qc] = Ub[c];
        }

#pragma unroll
    for (int i = 0; i < 2; i++)
#pragma unroll
        for (int qr = 0; qr < 2; qr++) {
            int row = m0 + warp_m + i * 16 + lane4 + qr * 8;
            int b = row & (Bq - 1);
            const float* hwr = g_hW + (size_t)b * Hq + n0 + warp_n + 2 * lanek;
            float part = 0.f;
#pragma unroll
            for (int j = 0; j < 8; j++)
#pragma unroll
                for (int qc = 0; qc < 2; qc++) {
                    float t = acc[i][j][2 * qr + qc] + uu[j][qc]
                              + hwr[j * 8 + qc];
                    part += vv[j][qc] * tanh_fast(t);
                }
            part += __shfl_xor_sync(0xffffffffu, part, 1);
            part += __shfl_xor_sync(0xffffffffu, part, 2);
            if (lanek == 0)
                g_spart[(size_t)(blockIdx.x * 2 + (warp_n >> 6)) * SBq + row]
                    = part;
        }
}

// ================== legacy small GEMMs (unchanged from R3) ==================
__device__ __forceinline__ void mma_tf32(float c[4], const unsigned a[4],
                                         const unsigned b[2])
{
    asm volatile(
        "mma.sync.aligned.m16n8k8.row.col.f32.tf32.tf32.f32 "
        "{%0,%1,%2,%3}, {%4,%5,%6,%7}, {%8,%9}, {%0,%1,%2,%3};"
        : "+f"(c[0]), "+f"(c[1]), "+f"(c[2]), "+f"(c[3])
        : "r"(a[0]), "r"(a[1]), "r"(a[2]), "r"(a[3]), "r"(b[0]), "r"(b[1]));
}

// single-pass tf32 GEMM: C[M,N] = A[M,K] @ B[N,K]^T (+bias). N ragged.
template <int BM, int BN, int BK, int WM, int WN>
__global__ void __launch_bounds__(256)
mma_gemm_nt(const float* __restrict__ A, const float* __restrict__ Bm,
            float* __restrict__ C, int M, int N, int K,
            const float* __restrict__ bias)
{
    constexpr int MI = WM / 16;
    constexpr int NI = WN / 8;
    constexpr int KP = BK + 4;
    constexpr int F4R = BK / 4;
    constexpr int RPP = 256 / F4R;

    __shared__ unsigned As[BM][KP];
    __shared__ unsigned Bs[BN][KP];

    const int tid = threadIdx.x;
    const int lane = tid & 31;
    const int w = tid >> 5;
    const int warp_m = (w % (BM / WM)) * WM;
    const int warp_n = (w / (BM / WM)) * WN;
    const int m0 = blockIdx.y * BM;
    const int n0 = blockIdx.x * BN;
    const int lrow = tid / F4R;
    const int lk4 = (tid % F4R) * 4;

    float acc[MI][NI][4];
#pragma unroll
    for (int i = 0; i < MI; i++)
#pragma unroll
        for (int j = 0; j < NI; j++)
#pragma unroll
            for (int q = 0; q < 4; q++) acc[i][j][q] = 0.f;

    for (int k0 = 0; k0 < K; k0 += BK) {
#pragma unroll
        for (int r = lrow; r < BM; r += RPP) {
            float4 vv = *reinterpret_cast<const float4*>(
                A + (size_t)(m0 + r) * K + k0 + lk4);
            uint4 u;
            u.x = f2tf32(vv.x); u.y = f2tf32(vv.y);
            u.z = f2tf32(vv.z); u.w = f2tf32(vv.w);
            *reinterpret_cast<uint4*>(&As[r][lk4]) = u;
        }
#pragma unroll
        for (int r = lrow; r < BN; r += RPP) {
            float4 vv = make_float4(0.f, 0.f, 0.f, 0.f);
            if (n0 + r < N)
                vv = *reinterpret_cast<const float4*>(
                    Bm + (size_t)(n0 + r) * K + k0 + lk4);
            uint4 u;
            u.x = f2tf32(vv.x); u.y = f2tf32(vv.y);
            u.z = f2tf32(vv.z); u.w = f2tf32(vv.w);
            *reinterpret_cast<uint4*>(&Bs[r][lk4]) = u;
        }
        __syncthreads();

#pragma unroll
        for (int kk = 0; kk < BK; kk += 8) {
            unsigned af[MI][4], bf[NI][2];
#pragma unroll
            for (int i = 0; i < MI; i++) {
                int r = warp_m + i * 16 + (lane >> 2);
                int cb = kk + (lane & 3);
                af[i][0] = As[r][cb];     af[i][1] = As[r + 8][cb];
                af[i][2] = As[r][cb + 4]; af[i][3] = As[r + 8][cb + 4];
            }
#pragma unroll
            for (int j = 0; j < NI; j++) {
                int r = warp_n + j * 8 + (lane >> 2);
                int cb = kk + (lane & 3);
                bf[j][0] = Bs[r][cb]; bf[j][1] = Bs[r][cb + 4];
            }
#pragma unroll
            for (int i = 0; i < MI; i++)
#pragma unroll
                for (int j = 0; j < NI; j++)
                    mma_tf32(acc[i][j], af[i], bf[j]);
        }
        __syncthreads();
    }

#pragma unroll
    for (int i = 0; i < MI; i++)
#pragma unroll
        for (int j = 0; j < NI; j++) {
            int row = m0 + warp_m + i * 16 + (lane >> 2);
            int col = n0 + warp_n + j * 8 + 2 * (lane & 3);
#pragma unroll
            for (int q = 0; q < 4; q++) {
                int gr = row + (q >> 1) * 8;
                int gc = col + (q & 1);
                if (gc < N) {
                    float r = acc[i][j][q];
                    if (bias) r += bias[gc];
                    C[(size_t)gr * N + gc] = r;
                }
            }
        }
}

// 3xTF32 legacy GEMM (accurate): C = A@B^T (+bias)(+=C)
template <int BM, int BN, int BK, int WM, int WN>
__global__ void __launch_bounds__(256)
mma3_gemm_nt(const float* __restrict__ A, const float* __restrict__ Bm,
             float* __restrict__ C, int M, int N, int K,
             const float* __restrict__ bias, int accum)
{
    constexpr int MI = WM / 16;
    constexpr int NI = WN / 8;
    constexpr int KP = BK + 4;
    constexpr int F4R = BK / 4;
    constexpr int RPP = 256 / F4R;

    __shared__ unsigned Ah[BM][KP], Al[BM][KP];
    __shared__ unsigned Bh[BN][KP], Bl[BN][KP];

    const int tid = threadIdx.x;
    const int lane = tid & 31;
    const int w = tid >> 5;
    const int warp_m = (w % (BM / WM)) * WM;
    const int warp_n = (w / (BM / WM)) * WN;
    const int m0 = blockIdx.y * BM;
    const int n0 = blockIdx.x * BN;
    const int lrow = tid / F4R;
    const int lk4 = (tid % F4R) * 4;

    float acc[MI][NI][4];
#pragma unroll
    for (int i = 0; i < MI; i++)
#pragma unroll
        for (int j = 0; j < NI; j++)
#pragma unroll
            for (int q = 0; q < 4; q++) acc[i][j][q] = 0.f;

    for (int k0 = 0; k0 < K; k0 += BK) {
#pragma unroll
        for (int r = lrow; r < BM; r += RPP) {
            float4 vv = *reinterpret_cast<const float4*>(
                A + (size_t)(m0 + r) * K + k0 + lk4);
            uint4 uh, ul;
            split_tf32(vv.x, uh.x, ul.x); split_tf32(vv.y, uh.y, ul.y);
            split_tf32(vv.z, uh.z, ul.z); split_tf32(vv.w, uh.w, ul.w);
            *reinterpret_cast<uint4*>(&Ah[r][lk4]) = uh;
            *reinterpret_cast<uint4*>(&Al[r][lk4]) = ul;
        }
#pragma unroll
        for (int r = lrow; r < BN; r += RPP) {
            float4 vv = make_float4(0.f, 0.f, 0.f, 0.f);
            if (n0 + r < N)
                vv = *reinterpret_cast<const float4*>(
                    Bm + (size_t)(n0 + r) * K + k0 + lk4);
            uint4 uh, ul;
            split_tf32(vv.x, uh.x, ul.x); split_tf32(vv.y, uh.y, ul.y);
            split_tf32(vv.z, uh.z, ul.z); split_tf32(vv.w, uh.w, ul.w);
            *reinterpret_cast<uint4*>(&Bh[r][lk4]) = uh;
            *reinterpret_cast<uint4*>(&Bl[r][lk4]) = ul;
        }
        __syncthreads();

#pragma unroll
        for (int kk = 0; kk < BK; kk += 8) {
            unsigned ah[MI][4], al[MI][4], bh[NI][2], bl[NI][2];
#pragma unroll
            for (int i = 0; i < MI; i++) {
                int r = warp_m + i * 16 + (lane >> 2);
                int cb = kk + (lane & 3);
                ah[i][0] = Ah[r][cb];     ah[i][1] = Ah[r + 8][cb];
                ah[i][2] = Ah[r][cb + 4]; ah[i][3] = Ah[r + 8][cb + 4];
                al[i][0] = Al[r][cb];     al[i][1] = Al[r + 8][cb];
                al[i][2] = Al[r][cb + 4]; al[i][3] = Al[r + 8][cb + 4];
            }
#pragma unroll
            for (int j = 0; j < NI; j++) {
                int r = warp_n + j * 8 + (lane >> 2);
                int cb = kk + (lane & 3);
                bh[j][0] = Bh[r][cb]; bh[j][1] = Bh[r][cb + 4];
                bl[j][0] = Bl[r][cb]; bl[j][1] = Bl[r][cb + 4];
            }
#pragma unroll
            for (int i = 0; i < MI; i++)
#pragma unroll
                for (int j = 0; j < NI; j++) {
                    mma_tf32(acc[i][j], ah[i], bl[j]);
                    mma_tf32(acc[i][j], al[i], bh[j]);
                    mma_tf32(acc[i][j], ah[i], bh[j]);
                }
        }
        __syncthreads();
    }

#pragma unroll
    for (int i = 0; i < MI; i++)
#pragma unroll
        for (int j = 0; j < NI; j++) {
            int row = m0 + warp_m + i * 16 + (lane >> 2);
            int col = n0 + warp_n + j * 8 + 2 * (lane & 3);
#pragma unroll
            for (int q = 0; q < 4; q++) {
                int gr = row + (q >> 1) * 8;
                int gc = col + (q & 1);
                if (gc < N) {
                    float r = acc[i][j][q];
                    if (bias) r += bias[gc];
                    size_t off = (size_t)gr * N + gc;
                    if (accum) r += C[off];
                    C[off] = r;
                }
            }
        }
}

// ---------------- pointwise / reduction kernels -----------------------------
__global__ void softmax_kernel(float* __restrict__ attn_out)
{
    __shared__ float sm[Sq];
    int b = blockIdx.x, t = threadIdx.x;
    float x = 0.f;
#pragma unroll
    for (int q = 0; q < NSLOT; q++)
        x += g_spart[(size_t)q * SBq + t * Bq + b];
    sm[t] = x; __syncthreads();
    for (int o = 64; o > 0; o >>= 1) {
        if (t < o) sm[t] = fmaxf(sm[t], sm[t + o]);
        __syncthreads();
    }
    float m = sm[0];
    __syncthreads();
    float e = expf(x - m);
    sm[t] = e; __syncthreads();
    for (int o = 64; o > 0; o >>= 1) {
        if (t < o) sm[t] += sm[t + o];
        __syncthreads();
    }
    attn_out[b * Sq + t] = e / sm[0];
}

__global__ void context_kernel(const float* __restrict__ attn,
                               const float* __restrict__ enc)
{
    __shared__ float aw[Sq];
    int idx = blockIdx.x * 256 + threadIdx.x;
    int b = idx >> 10;
    int h = idx & (Hq - 1);
    if (threadIdx.x < Sq) aw[threadIdx.x] = attn[b * Sq + threadIdx.x];
    __syncthreads();
    float acc = 0.f;
#pragma unroll 4
    for (int s = 0; s < Sq; s++)
        acc = fmaf(aw[s], enc[((size_t)s * Bq + b) * Hq + h], acc);
    g_ctx[idx] = acc;
}

__global__ void xbuild_kernel(const int* __restrict__ seq,
                              const float* __restrict__ emb)
{
    int idx = blockIdx.x * 256 + threadIdx.x;
    int b = idx / KIq;
    int j = idx - b * KIq;
    float val;
    if (j < Eq) val = emb[(size_t)seq[b] * Eq + j];
    else        val = g_ctx[b * Hq + (j - Eq)];
    g_x[idx] = val;
}

__device__ __forceinline__ float sigf(float x) { return 1.f / (1.f + expf(-x)); }

__global__ void lstm_kernel(const float* __restrict__ c0,
                            float* __restrict__ h_new,
                            float* __restrict__ c_new)
{
    int idx = blockIdx.x * 256 + threadIdx.x;
    int b = idx >> 10;
    int h = idx & (Hq - 1);
    const float* g = g_gates + ((size_t)b << 12);
    float vi = g[h];
    float vf = g[Hq + h];
    float vg = g[2 * Hq + h];
    float vo = g[3 * Hq + h];
    float c = sigf(vf) * c0[idx] + sigf(vi) * tanhf(vg);
    c_new[idx] = c;
    h_new[idx] = sigf(vo) * tanhf(c);
}

__device__ __forceinline__ float blk_red_max(float v, float* red)
{
    int t = threadIdx.x;
#pragma unroll
    for (int o = 16; o > 0; o >>= 1) v = fmaxf(v, __shfl_xor_sync(~0u, v, o));
    if ((t & 31) == 0) red[t >> 5] = v;
    __syncthreads();
    if (t < 32) {
        v = red[t];
#pragma unroll
        for (int o = 16; o > 0; o >>= 1) v = fmaxf(v, __shfl_xor_sync(~0u, v, o));
        if (t == 0) red[0] = v;
    }
    __syncthreads();
    float r = red[0];
    __syncthreads();
    return r;
}

__device__ __forceinline__ float blk_red_sum(float v, float* red)
{
    int t = threadIdx.x;
#pragma unroll
    for (int o = 16; o > 0; o >>= 1) v += __shfl_xor_sync(~0u, v, o);
    if ((t & 31) == 0) red[t >> 5] = v;
    __syncthreads();
    if (t < 32) {
        v = red[t];
#pragma unroll
        for (int o = 16; o > 0; o >>= 1) v += __shfl_xor_sync(~0u, v, o);
        if (t == 0) red[0] = v;
    }
    __syncthreads();
    float r = red[0];
    __syncthreads();
    return r;
}

__global__ void logsoftmax_kernel(float* __restrict__ out)
{
    __shared__ float red[32];
    int b = blockIdx.x;
    float* row = out + (size_t)b * Vq;
    int t = threadIdx.x;

    float m = -1e30f;
    for (int j = t; j < Vq; j += 1024) m = fmaxf(m, row[j]);
    m = blk_red_max(m, red);

    float s = 0.f;
    for (int j = t; j < Vq; j += 1024) s += expf(row[j] - m);
    s = blk_red_sum(s, red);

    float lse = m + logf(s);
    for (int j = t; j < Vq; j += 1024) row[j] -= lse;
}

// ---------------------------------------------------------------------------
extern "C" void kernel_launch(void* const* d_in, const int* in_sizes, int n_in,
                              void* d_out, int out_size)
{
    const int*   seq     = (const int*)d_in[0];
    const float* h0      = (const float*)d_in[1];
    const float* c0      = (const float*)d_in[2];
    const float* enc     = (const float*)d_in[3];
    const float* emb     = (const float*)d_in[4];
    const float* W_ih    = (const float*)d_in[5];
    const float* W_hh    = (const float*)d_in[6];
    const float* b_ih    = (const float*)d_in[7];
    const float* b_hh    = (const float*)d_in[8];
    const float* attn_W  = (const float*)d_in[9];
    const float* attn_Wb = (const float*)d_in[10];
    const float* attn_U  = (const float*)d_in[11];
    const float* attn_Ub = (const float*)d_in[12];
    const float* attn_v  = (const float*)d_in[13];
    const float* out_W   = (const float*)d_in[14];
    const float* out_b   = (const float*)d_in[15];

    float* out      = (float*)d_out;
    float* o_logits = out;                          // [B, V]
    float* o_h      = out + (size_t)Bq * Vq;        // [1, B, H]
    float* o_c      = o_h + Bq * Hq;                // [1, B, H]
    float* o_attn   = o_c + Bq * Hq;                // [B, 1, S]

    float *hW, *x, *gates;
    cudaGetSymbolAddress((void**)&hW,    g_hW);
    cudaGetSymbolAddress((void**)&x,     g_x);
    cudaGetSymbolAddress((void**)&gates, g_gates);

    cudaFuncSetAttribute(tgemm_score_kernel,
                         cudaFuncAttributeMaxDynamicSharedMemorySize, TSMEM);

    // 1) hW = h0 @ attn_W^T + attn_Wb            [64, 1024]   (3xTF32 legacy)
    mma3_gemm_nt<64, 128, 16, 32, 32><<<dim3(Hq / 128, 1), 256>>>(
        h0, attn_W, hW, Bq, Hq, Hq, attn_Wb, 0);

    // 2) fused energy GEMM (3xTF32, packed hi/lo) + score partials
    tgemm_score_kernel<<<dim3(Hq / 128, SBq / 128), 256, TSMEM>>>(
        enc, attn_U, attn_Ub, attn_v);

    // 3) attn = softmax(reduce(spart)) -> output region
    softmax_kernel<<<Bq, Sq>>>(o_attn);

    // 4) context = attn @ enc                    [64, 1024]
    context_kernel<<<Bq * Hq / 256, 256>>>(o_attn, enc);

    // 5) x = [emb[seq] ; context]                [64, 1536]
    xbuild_kernel<<<Bq * KIq / 256, 256>>>(seq, emb);

    // 6) gates  = x @ W_ih^T + b_ih              [64, 4096]   (3xTF32 legacy)
    mma3_gemm_nt<64, 128, 16, 32, 32><<<dim3(G4q / 128, 1), 256>>>(
        x, W_ih, gates, Bq, G4q, KIq, b_ih, 0);

    // 7) gates += h0 @ W_hh^T + b_hh                          (3xTF32 legacy)
    mma3_gemm_nt<64, 128, 16, 32, 32><<<dim3(G4q / 128, 1), 256>>>(
        h0, W_hh, gates, Bq, G4q, Hq, b_hh, 1);

    // 8) LSTM pointwise -> h_new, c_new in output
    lstm_kernel<<<Bq * Hq / 256, 256>>>(c0, o_h, o_c);

    // 9) logits = h_new @ out_W^T + out_b        [64, 50257]  (single tf32)
    mma_gemm_nt<64, 128, 32, 32, 32><<<dim3((Vq + 127) / 128, 1), 256>>>(
        o_h, out_W, o_logits, Bq, Vq, Hq, out_b);

    // 10) in-place log_softmax over V
    logsoftmax_kernel<<<Bq, 1024>>>(o_logits);
}

// round 7
// speedup vs baseline: 1.6274x; 1.6274x over previous
#include <cuda_runtime.h>
#include <cuda_bf16.h>
#include <math.h>
#include <stdint.h>

#define Bq 64
#define Sq 128
#define Eq 512
#define Hq 1024
#define Vq 50257
#define KIq (Eq + Hq)   /* 1536 */
#define G4q (4 * Hq)    /* 4096 */
#define SBq (Sq * Bq)   /* 8192 */
#define NSLOT 32

// ---------------- scratch (static device globals; no runtime allocation) ----
__device__ float g_hW[Bq * Hq];
__device__ float g_spart[NSLOT * SBq];  // score column-partials per (s,b) row
__device__ float g_ctx[Bq * Hq];
__device__ float g_x[Bq * KIq];
__device__ float g_gates[Bq * G4q];

// ---------------- precision helpers -----------------------------------------
__device__ __forceinline__ unsigned f2tf32(float x)
{
    unsigned r;
    asm("cvt.rna.tf32.f32 %0, %1;" : "=r"(r) : "f"(x));
    return r;
}

__device__ __forceinline__ void split_bf16(float x, float& hi, float& lo)
{
    hi = __bfloat162float(__float2bfloat16(x));
    lo = x - hi;
}

// pack two floats as bf16x2: low 16 bits = e0, high = e1
__device__ __forceinline__ unsigned pack2(float e0, float e1)
{
    unsigned r;
    asm("cvt.rn.bf16x2.f32 %0, %1, %2;" : "=r"(r) : "f"(e1), "f"(e0));
    return r;
}

__device__ __forceinline__ void mma_bf16(float c[4], const unsigned a[4],
                                         const unsigned b[2])
{
    asm volatile(
        "mma.sync.aligned.m16n8k16.row.col.f32.bf16.bf16.f32 "
        "{%0,%1,%2,%3}, {%4,%5,%6,%7}, {%8,%9}, {%0,%1,%2,%3};"
        : "+f"(c[0]), "+f"(c[1]), "+f"(c[2]), "+f"(c[3])
        : "r"(a[0]), "r"(a[1]), "r"(a[2]), "r"(a[3]), "r"(b[0]), "r"(b[1]));
}

__device__ __forceinline__ void mma_tf32(float c[4], const unsigned a[4],
                                         const unsigned b[2])
{
    asm volatile(
        "mma.sync.aligned.m16n8k8.row.col.f32.tf32.tf32.f32 "
        "{%0,%1,%2,%3}, {%4,%5,%6,%7}, {%8,%9}, {%0,%1,%2,%3};"
        : "+f"(c[0]), "+f"(c[1]), "+f"(c[2]), "+f"(c[3])
        : "r"(a[0]), "r"(a[1]), "r"(a[2]), "r"(a[3]), "r"(b[0]), "r"(b[1]));
}

__device__ __forceinline__ float tanh_fast(float x)
{
    float cx = fminf(fmaxf(x, -15.f), 15.f);
    float e = __expf(2.f * cx);
    return __fdividef(e - 1.f, e + 1.f);
}

// ================== 3xBF16 GEMM template (hi/lo compensated) ================
// C[M,N] = A[M,K] @ B[N,K]^T (+bias)(+=C). M%BM==0, K%BK==0, N ragged.
// Smem holds bf16 PAIRS (k even/odd packed in uint32); fragment addressing is
// identical to the tf32 path with pair-index in place of k-index.
template <int BM, int BN, int BK, int WM, int WN>
__global__ void __launch_bounds__(256)
mma3bf_gemm_nt(const float* __restrict__ A, const float* __restrict__ Bm,
               float* __restrict__ C, int M, int N, int K,
               const float* __restrict__ bias, int accum)
{
    constexpr int MI = WM / 16;
    constexpr int NI = WN / 8;
    constexpr int PP = BK / 2;          // pairs per row
    constexpr int KPP = PP + 4;         // padded pairs
    constexpr int F4R = BK / 4;         // float4 loads per row
    constexpr int RPP = 256 / F4R;

    __shared__ unsigned Ah[BM][KPP], Al[BM][KPP];
    __shared__ unsigned Bh[BN][KPP], Bl[BN][KPP];

    const int tid = threadIdx.x;
    const int lane = tid & 31;
    const int w = tid >> 5;
    const int warp_m = (w % (BM / WM)) * WM;
    const int warp_n = (w / (BM / WM)) * WN;
    const int m0 = blockIdx.y * BM;
    const int n0 = blockIdx.x * BN;
    const int lrow = tid / F4R;
    const int lk4 = (tid % F4R) * 4;    // float offset
    const int lp = lk4 >> 1;            // pair offset

    float acc[MI][NI][4];
#pragma unroll
    for (int i = 0; i < MI; i++)
#pragma unroll
        for (int j = 0; j < NI; j++)
#pragma unroll
            for (int q = 0; q < 4; q++) acc[i][j][q] = 0.f;

    for (int k0 = 0; k0 < K; k0 += BK) {
#pragma unroll
        for (int r = lrow; r < BM; r += RPP) {
            float4 vv = *reinterpret_cast<const float4*>(
                A + (size_t)(m0 + r) * K + k0 + lk4);
            float hx, lx, hy, ly, hz, lz, hw, lw;
            split_bf16(vv.x, hx, lx); split_bf16(vv.y, hy, ly);
            split_bf16(vv.z, hz, lz); split_bf16(vv.w, hw, lw);
            Ah[r][lp] = pack2(hx, hy); Ah[r][lp + 1] = pack2(hz, hw);
            Al[r][lp] = pack2(lx, ly); Al[r][lp + 1] = pack2(lz, lw);
        }
#pragma unroll
        for (int r = lrow; r < BN; r += RPP) {
            float4 vv = make_float4(0.f, 0.f, 0.f, 0.f);
            if (n0 + r < N)
                vv = *reinterpret_cast<const float4*>(
                    Bm + (size_t)(n0 + r) * K + k0 + lk4);
            float hx, lx, hy, ly, hz, lz, hw, lw;
            split_bf16(vv.x, hx, lx); split_bf16(vv.y, hy, ly);
            split_bf16(vv.z, hz, lz); split_bf16(vv.w, hw, lw);
            Bh[r][lp] = pack2(hx, hy); Bh[r][lp + 1] = pack2(hz, hw);
            Bl[r][lp] = pack2(lx, ly); Bl[r][lp + 1] = pack2(lz, lw);
        }
        __syncthreads();

#pragma unroll
        for (int kk = 0; kk < PP; kk += 8) {
            unsigned ah[MI][4], al[MI][4], bh[NI][2], bl[NI][2];
#pragma unroll
            for (int i = 0; i < MI; i++) {
                int r = warp_m + i * 16 + (lane >> 2);
                int cb = kk + (lane & 3);
                ah[i][0] = Ah[r][cb];     ah[i][1] = Ah[r + 8][cb];
                ah[i][2] = Ah[r][cb + 4]; ah[i][3] = Ah[r + 8][cb + 4];
                al[i][0] = Al[r][cb];     al[i][1] = Al[r + 8][cb];
                al[i][2] = Al[r][cb + 4]; al[i][3] = Al[r + 8][cb + 4];
            }
#pragma unroll
            for (int j = 0; j < NI; j++) {
                int r = warp_n + j * 8 + (lane >> 2);
                int cb = kk + (lane & 3);
                bh[j][0] = Bh[r][cb]; bh[j][1] = Bh[r][cb + 4];
                bl[j][0] = Bl[r][cb]; bl[j][1] = Bl[r][cb + 4];
            }
#pragma unroll
            for (int i = 0; i < MI; i++)
#pragma unroll
                for (int j = 0; j < NI; j++) {
                    mma_bf16(acc[i][j], ah[i], bl[j]);
                    mma_bf16(acc[i][j], al[i], bh[j]);
                    mma_bf16(acc[i][j], ah[i], bh[j]);
                }
        }
        __syncthreads();
    }

#pragma unroll
    for (int i = 0; i < MI; i++)
#pragma unroll
        for (int j = 0; j < NI; j++) {
            int row = m0 + warp_m + i * 16 + (lane >> 2);
            int col = n0 + warp_n + j * 8 + 2 * (lane & 3);
#pragma unroll
            for (int q = 0; q < 4; q++) {
                int gr = row + (q >> 1) * 8;
                int gc = col + (q & 1);
                if (gc < N) {
                    float r = acc[i][j][q];
                    if (bias) r += bias[gc];
                    size_t off = (size_t)gr * N + gc;
                    if (accum) r += C[off];
                    C[off] = r;
                }
            }
        }
}

// ============ 3xBF16 energy GEMM + fused score epilogue =====================
// T = enc[8192,1024] @ U[1024,1024]^T; epilogue: partial score
// sum_cols v * tanh(T + Ub + hW) per row, 32 deterministic slots.
// BM=BN=128, BK=32, WM=64, WN=32 (warp grid 2x4), 256 threads.
__global__ void __launch_bounds__(256)
tgemm_score_kernel(const float* __restrict__ enc, const float* __restrict__ U,
                   const float* __restrict__ Ub, const float* __restrict__ v)
{
    constexpr int BM = 128, BN = 128, BK = 32, WM = 64, WN = 32;
    constexpr int MI = WM / 16;         // 4
    constexpr int NI = WN / 8;          // 4
    constexpr int PP = BK / 2;          // 16
    constexpr int KPP = PP + 4;         // 20
    constexpr int F4R = BK / 4;         // 8
    constexpr int RPP = 256 / F4R;      // 32

    __shared__ unsigned Ah[BM][KPP], Al[BM][KPP];
    __shared__ unsigned Bh[BN][KPP], Bl[BN][KPP];

    const int tid = threadIdx.x;
    const int lane = tid & 31;
    const int w = tid >> 5;
    const int lane4 = lane >> 2;
    const int lanek = lane & 3;
    const int warp_m = (w % 2) * WM;
    const int warp_n = (w / 2) * WN;
    const int m0 = blockIdx.y * BM;
    const int n0 = blockIdx.x * BN;
    const int lrow = tid / F4R;
    const int lk4 = (tid % F4R) * 4;
    const int lp = lk4 >> 1;

    float acc[MI][NI][4];
#pragma unroll
    for (int i = 0; i < MI; i++)
#pragma unroll
        for (int j = 0; j < NI; j++)
#pragma unroll
            for (int q = 0; q < 4; q++) acc[i][j][q] = 0.f;

    for (int k0 = 0; k0 < Hq; k0 += BK) {
#pragma unroll
        for (int r = lrow; r < BM; r += RPP) {
            float4 vv = *reinterpret_cast<const float4*>(
                enc + (size_t)(m0 + r) * Hq + k0 + lk4);
            float hx, lx, hy, ly, hz, lz, hw, lw;
            split_bf16(vv.x, hx, lx); split_bf16(vv.y, hy, ly);
            split_bf16(vv.z, hz, lz); split_bf16(vv.w, hw, lw);
            Ah[r][lp] = pack2(hx, hy); Ah[r][lp + 1] = pack2(hz, hw);
            Al[r][lp] = pack2(lx, ly); Al[r][lp + 1] = pack2(lz, lw);
        }
#pragma unroll
        for (int r = lrow; r < BN; r += RPP) {
            float4 vv = *reinterpret_cast<const float4*>(
                U + (size_t)(n0 + r) * Hq + k0 + lk4);
            float hx, lx, hy, ly, hz, lz, hw, lw;
            split_bf16(vv.x, hx, lx); split_bf16(vv.y, hy, ly);
            split_bf16(vv.z, hz, lz); split_bf16(vv.w, hw, lw);
            Bh[r][lp] = pack2(hx, hy); Bh[r][lp + 1] = pack2(hz, hw);
            Bl[r][lp] = pack2(lx, ly); Bl[r][lp + 1] = pack2(lz, lw);
        }
        __syncthreads();

#pragma unroll
        for (int kk = 0; kk < PP; kk += 8) {
            unsigned ah[MI][4], al[MI][4], bh[NI][2], bl[NI][2];
#pragma unroll
            for (int i = 0; i < MI; i++) {
                int r = warp_m + i * 16 + lane4;
                int cb = kk + lanek;
                ah[i][0] = Ah[r][cb];     ah[i][1] = Ah[r + 8][cb];
                ah[i][2] = Ah[r][cb + 4]; ah[i][3] = Ah[r + 8][cb + 4];
                al[i][0] = Al[r][cb];     al[i][1] = Al[r + 8][cb];
                al[i][2] = Al[r][cb + 4]; al[i][3] = Al[r + 8][cb + 4];
            }
#pragma unroll
            for (int j = 0; j < NI; j++) {
                int r = warp_n + j * 8 + lane4;
                int cb = kk + lanek;
                bh[j][0] = Bh[r][cb]; bh[j][1] = Bh[r][cb + 4];
                bl[j][0] = Bl[r][cb]; bl[j][1] = Bl[r][cb + 4];
            }
#pragma unroll
            for (int i = 0; i < MI; i++)
#pragma unroll
                for (int j = 0; j < NI; j++) {
                    mma_bf16(acc[i][j], ah[i], bl[j]);
                    mma_bf16(acc[i][j], al[i], bh[j]);
                    mma_bf16(acc[i][j], ah[i], bh[j]);
                }
        }
        __syncthreads();
    }

    // ---- fused score epilogue over this warp's 32 columns ------------------
    float vv[NI][2], uu[NI][2];
#pragma unroll
    for (int j = 0; j < NI; j++)
#pragma unroll
        for (int qc = 0; qc < 2; qc++) {
            int c = n0 + warp_n + j * 8 + 2 * lanek + qc;
            vv[j][qc] = v[c];
            uu[j][qc] = Ub[c];
        }

    const int slot = blockIdx.x * 4 + (w / 2);
#pragma unroll
    for (int i = 0; i < MI; i++)
#pragma unroll
        for (int qr = 0; qr < 2; qr++) {
            int row = m0 + warp_m + i * 16 + lane4 + qr * 8;
            int b = row & (Bq - 1);
            const float* hwr = g_hW + (size_t)b * Hq + n0 + warp_n + 2 * lanek;
            float part = 0.f;
#pragma unroll
            for (int j = 0; j < NI; j++)
#pragma unroll
                for (int qc = 0; qc < 2; qc++) {
                    float t = acc[i][j][2 * qr + qc] + uu[j][qc]
                              + hwr[j * 8 + qc];
                    part += vv[j][qc] * tanh_fast(t);
                }
            part += __shfl_xor_sync(0xffffffffu, part, 1);
            part += __shfl_xor_sync(0xffffffffu, part, 2);
            if (lanek == 0)
                g_spart[(size_t)slot * SBq + row] = part;
        }
}

// ================== single-pass tf32 GEMM (logits) ==========================
template <int BM, int BN, int BK, int WM, int WN>
__global__ void __launch_bounds__(256)
mma_gemm_nt(const float* __restrict__ A, const float* __restrict__ Bm,
            float* __restrict__ C, int M, int N, int K,
            const float* __restrict__ bias)
{
    constexpr int MI = WM / 16;
    constexpr int NI = WN / 8;
    constexpr int KP = BK + 4;
    constexpr int F4R = BK / 4;
    constexpr int RPP = 256 / F4R;

    __shared__ unsigned As[BM][KP];
    __shared__ unsigned Bs[BN][KP];

    const int tid = threadIdx.x;
    const int lane = tid & 31;
    const int w = tid >> 5;
    const int warp_m = (w % (BM / WM)) * WM;
    const int warp_n = (w / (BM / WM)) * WN;
    const int m0 = blockIdx.y * BM;
    const int n0 = blockIdx.x * BN;
    const int lrow = tid / F4R;
    const int lk4 = (tid % F4R) * 4;

    float acc[MI][NI][4];
#pragma unroll
    for (int i = 0; i < MI; i++)
#pragma unroll
        for (int j = 0; j < NI; j++)
#pragma unroll
            for (int q = 0; q < 4; q++) acc[i][j][q] = 0.f;

    for (int k0 = 0; k0 < K; k0 += BK) {
#pragma unroll
        for (int r = lrow; r < BM; r += RPP) {
            float4 vv = *reinterpret_cast<const float4*>(
                A + (size_t)(m0 + r) * K + k0 + lk4);
            uint4 u;
            u.x = f2tf32(vv.x); u.y = f2tf32(vv.y);
            u.z = f2tf32(vv.z); u.w = f2tf32(vv.w);
            *reinterpret_cast<uint4*>(&As[r][lk4]) = u;
        }
#pragma unroll
        for (int r = lrow; r < BN; r += RPP) {
            float4 vv = make_float4(0.f, 0.f, 0.f, 0.f);
            if (n0 + r < N)
                vv = *reinterpret_cast<const float4*>(
                    Bm + (size_t)(n0 + r) * K + k0 + lk4);
            uint4 u;
            u.x = f2tf32(vv.x); u.y = f2tf32(vv.y);
            u.z = f2tf32(vv.z); u.w = f2tf32(vv.w);
            *reinterpret_cast<uint4*>(&Bs[r][lk4]) = u;
        }
        __syncthreads();

#pragma unroll
        for (int kk = 0; kk < BK; kk += 8) {
            unsigned af[MI][4], bf[NI][2];
#pragma unroll
            for (int i = 0; i < MI; i++) {
                int r = warp_m + i * 16 + (lane >> 2);
                int cb = kk + (lane & 3);
                af[i][0] = As[r][cb];     af[i][1] = As[r + 8][cb];
                af[i][2] = As[r][cb + 4]; af[i][3] = As[r + 8][cb + 4];
            }
#pragma unroll
            for (int j = 0; j < NI; j++) {
                int r = warp_n + j * 8 + (lane >> 2);
                int cb = kk + (lane & 3);
                bf[j][0] = Bs[r][cb]; bf[j][1] = Bs[r][cb + 4];
            }
#pragma unroll
            for (int i = 0; i < MI; i++)
#pragma unroll
                for (int j = 0; j < NI; j++)
                    mma_tf32(acc[i][j], af[i], bf[j]);
        }
        __syncthreads();
    }

#pragma unroll
    for (int i = 0; i < MI; i++)
#pragma unroll
        for (int j = 0; j < NI; j++) {
            int row = m0 + warp_m + i * 16 + (lane >> 2);
            int col = n0 + warp_n + j * 8 + 2 * (lane & 3);
#pragma unroll
            for (int q = 0; q < 4; q++) {
                int gr = row + (q >> 1) * 8;
                int gc = col + (q & 1);
                if (gc < N) {
                    float r = acc[i][j][q];
                    if (bias) r += bias[gc];
                    C[(size_t)gr * N + gc] = r;
                }
            }
        }
}

// ---------------- pointwise / reduction kernels -----------------------------
__global__ void softmax_kernel(float* __restrict__ attn_out)
{
    __shared__ float sm[Sq];
    int b = blockIdx.x, t = threadIdx.x;
    float x = 0.f;
#pragma unroll
    for (int q = 0; q < NSLOT; q++)
        x += g_spart[(size_t)q * SBq + t * Bq + b];
    sm[t] = x; __syncthreads();
    for (int o = 64; o > 0; o >>= 1) {
        if (t < o) sm[t] = fmaxf(sm[t], sm[t + o]);
        __syncthreads();
    }
    float m = sm[0];
    __syncthreads();
    float e = expf(x - m);
    sm[t] = e; __syncthreads();
    for (int o = 64; o > 0; o >>= 1) {
        if (t < o) sm[t] += sm[t + o];
        __syncthreads();
    }
    attn_out[b * Sq + t] = e / sm[0];
}

__global__ void context_kernel(const float* __restrict__ attn,
                               const float* __restrict__ enc)
{
    __shared__ float aw[Sq];
    int idx = blockIdx.x * 256 + threadIdx.x;
    int b = idx >> 10;
    int h = idx & (Hq - 1);
    if (threadIdx.x < Sq) aw[threadIdx.x] = attn[b * Sq + threadIdx.x];
    __syncthreads();
    float acc = 0.f;
#pragma unroll 4
    for (int s = 0; s < Sq; s++)
        acc = fmaf(aw[s], enc[((size_t)s * Bq + b) * Hq + h], acc);
    g_ctx[idx] = acc;
}

__global__ void xbuild_kernel(const int* __restrict__ seq,
                              const float* __restrict__ emb)
{
    int idx = blockIdx.x * 256 + threadIdx.x;
    int b = idx / KIq;
    int j = idx - b * KIq;
    float val;
    if (j < Eq) val = emb[(size_t)seq[b] * Eq + j];
    else        val = g_ctx[b * Hq + (j - Eq)];
    g_x[idx] = val;
}

__device__ __forceinline__ float sigf(float x) { return 1.f / (1.f + expf(-x)); }

__global__ void lstm_kernel(const float* __restrict__ c0,
                            float* __restrict__ h_new,
                            float* __restrict__ c_new)
{
    int idx = blockIdx.x * 256 + threadIdx.x;
    int b = idx >> 10;
    int h = idx & (Hq - 1);
    const float* g = g_gates + ((size_t)b << 12);
    float vi = g[h];
    float vf = g[Hq + h];
    float vg = g[2 * Hq + h];
    float vo = g[3 * Hq + h];
    float c = sigf(vf) * c0[idx] + sigf(vi) * tanhf(vg);
    c_new[idx] = c;
    h_new[idx] = sigf(vo) * tanhf(c);
}

__device__ __forceinline__ float blk_red_max(float v, float* red)
{
    int t = threadIdx.x;
#pragma unroll
    for (int o = 16; o > 0; o >>= 1) v = fmaxf(v, __shfl_xor_sync(~0u, v, o));
    if ((t & 31) == 0) red[t >> 5] = v;
    __syncthreads();
    if (t < 32) {
        v = red[t];
#pragma unroll
        for (int o = 16; o > 0; o >>= 1) v = fmaxf(v, __shfl_xor_sync(~0u, v, o));
        if (t == 0) red[0] = v;
    }
    __syncthreads();
    float r = red[0];
    __syncthreads();
    return r;
}

__device__ __forceinline__ float blk_red_sum(float v, float* red)
{
    int t = threadIdx.x;
#pragma unroll
    for (int o = 16; o > 0; o >>= 1) v += __shfl_xor_sync(~0u, v, o);
    if ((t & 31) == 0) red[t >> 5] = v;
    __syncthreads();
    if (t < 32) {
        v = red[t];
#pragma unroll
        for (int o = 16; o > 0; o >>= 1) v += __shfl_xor_sync(~0u, v, o);
        if (t == 0) red[0] = v;
    }
    __syncthreads();
    float r = red[0];
    __syncthreads();
    return r;
}

__global__ void logsoftmax_kernel(float* __restrict__ out)
{
    __shared__ float red[32];
    int b = blockIdx.x;
    float* row = out + (size_t)b * Vq;
    int t = threadIdx.x;

    float m = -1e30f;
    for (int j = t; j < Vq; j += 1024) m = fmaxf(m, row[j]);
    m = blk_red_max(m, red);

    float s = 0.f;
    for (int j = t; j < Vq; j += 1024) s += expf(row[j] - m);
    s = blk_red_sum(s, red);

    float lse = m + logf(s);
    for (int j = t; j < Vq; j += 1024) row[j] -= lse;
}

// ---------------------------------------------------------------------------
extern "C" void kernel_launch(void* const* d_in, const int* in_sizes, int n_in,
                              void* d_out, int out_size)
{
    const int*   seq     = (const int*)d_in[0];
    const float* h0      = (const float*)d_in[1];
    const float* c0      = (const float*)d_in[2];
    const float* enc     = (const float*)d_in[3];
    const float* emb     = (const float*)d_in[4];
    const float* W_ih    = (const float*)d_in[5];
    const float* W_hh    = (const float*)d_in[6];
    const float* b_ih    = (const float*)d_in[7];
    const float* b_hh    = (const float*)d_in[8];
    const float* attn_W  = (const float*)d_in[9];
    const float* attn_Wb = (const float*)d_in[10];
    const float* attn_U  = (const float*)d_in[11];
    const float* attn_Ub = (const float*)d_in[12];
    const float* attn_v  = (const float*)d_in[13];
    const float* out_W   = (const float*)d_in[14];
    const float* out_b   = (const float*)d_in[15];

    float* out      = (float*)d_out;
    float* o_logits = out;                          // [B, V]
    float* o_h      = out + (size_t)Bq * Vq;        // [1, B, H]
    float* o_c      = o_h + Bq * Hq;                // [1, B, H]
    float* o_attn   = o_c + Bq * Hq;                // [B, 1, S]

    float *hW, *x, *gates;
    cudaGetSymbolAddress((void**)&hW,    g_hW);
    cudaGetSymbolAddress((void**)&x,     g_x);
    cudaGetSymbolAddress((void**)&gates, g_gates);

    // 1) hW = h0 @ attn_W^T + attn_Wb            [64, 1024]   (3xBF16)
    mma3bf_gemm_nt<64, 128, 32, 32, 32><<<dim3(Hq / 128, 1), 256>>>(
        h0, attn_W, hW, Bq, Hq, Hq, attn_Wb, 0);

    // 2) fused energy GEMM (3xBF16) + score partials
    tgemm_score_kernel<<<dim3(Hq / 128, SBq / 128), 256>>>(
        enc, attn_U, attn_Ub, attn_v);

    // 3) attn = softmax(reduce(spart)) -> output region
    softmax_kernel<<<Bq, Sq>>>(o_attn);

    // 4) context = attn @ enc                    [64, 1024]
    context_kernel<<<Bq * Hq / 256, 256>>>(o_attn, enc);

    // 5) x = [emb[seq] ; context]                [64, 1536]
    xbuild_kernel<<<Bq * KIq / 256, 256>>>(seq, emb);

    // 6) gates  = x @ W_ih^T + b_ih              [64, 4096]   (3xBF16)
    mma3bf_gemm_nt<64, 128, 32, 32, 32><<<dim3(G4q / 128, 1), 256>>>(
        x, W_ih, gates, Bq, G4q, KIq, b_ih, 0);

    // 7) gates += h0 @ W_hh^T + b_hh                          (3xBF16)
    mma3bf_gemm_nt<64, 128, 32, 32, 32><<<dim3(G4q / 128, 1), 256>>>(
        h0, W_hh, gates, Bq, G4q, Hq, b_hh, 1);

    // 8) LSTM pointwise -> h_new, c_new in output
    lstm_kernel<<<Bq * Hq / 256, 256>>>(c0, o_h, o_c);

    // 9) logits = h_new @ out_W^T + out_b        [64, 50257]  (single tf32)
    mma_gemm_nt<64, 128, 32, 32, 32><<<dim3((Vq + 127) / 128, 1), 256>>>(
        o_h, out_W, o_logits, Bq, Vq, Hq, out_b);

    // 10) in-place log_softmax over V
    logsoftmax_kernel<<<Bq, 1024>>>(o_logits);
}

// round 8
// speedup vs baseline: 1.8178x; 1.1170x over previous
#include <cuda_runtime.h>
#include <cuda_bf16.h>
#include <math.h>
#include <stdint.h>

#define Bq 64
#define Sq 128
#define Eq 512
#define Hq 1024
#define Vq 50257
#define KIq (Eq + Hq)   /* 1536 */
#define G4q (4 * Hq)    /* 4096 */
#define SBq (Sq * Bq)   /* 8192 */
#define NSLOT 32

// ---------------- scratch (static device globals; no runtime allocation) ----
__device__ float g_hW[Bq * Hq];
__device__ float g_spart[NSLOT * SBq];  // score column-partials per (s,b) row
__device__ float g_ctx[Bq * Hq];
__device__ float g_x[Bq * KIq];
__device__ float g_gates[Bq * G4q];

// ---------------- precision helpers -----------------------------------------
__device__ __forceinline__ unsigned f2tf32(float x)
{
    unsigned r;
    asm("cvt.rna.tf32.f32 %0, %1;" : "=r"(r) : "f"(x));
    return r;
}

__device__ __forceinline__ void split_bf16(float x, float& hi, float& lo)
{
    hi = __bfloat162float(__float2bfloat16(x));
    lo = x - hi;
}

// pack two floats as bf16x2: low 16 bits = e0, high = e1
__device__ __forceinline__ unsigned pack2(float e0, float e1)
{
    unsigned r;
    asm("cvt.rn.bf16x2.f32 %0, %1, %2;" : "=r"(r) : "f"(e1), "f"(e0));
    return r;
}

__device__ __forceinline__ void mma_bf16(float c[4], const unsigned a[4],
                                         const unsigned b[2])
{
    asm volatile(
        "mma.sync.aligned.m16n8k16.row.col.f32.bf16.bf16.f32 "
        "{%0,%1,%2,%3}, {%4,%5,%6,%7}, {%8,%9}, {%0,%1,%2,%3};"
        : "+f"(c[0]), "+f"(c[1]), "+f"(c[2]), "+f"(c[3])
        : "r"(a[0]), "r"(a[1]), "r"(a[2]), "r"(a[3]), "r"(b[0]), "r"(b[1]));
}

__device__ __forceinline__ void mma_tf32(float c[4], const unsigned a[4],
                                         const unsigned b[2])
{
    asm volatile(
        "mma.sync.aligned.m16n8k8.row.col.f32.tf32.tf32.f32 "
        "{%0,%1,%2,%3}, {%4,%5,%6,%7}, {%8,%9}, {%0,%1,%2,%3};"
        : "+f"(c[0]), "+f"(c[1]), "+f"(c[2]), "+f"(c[3])
        : "r"(a[0]), "r"(a[1]), "r"(a[2]), "r"(a[3]), "r"(b[0]), "r"(b[1]));
}

__device__ __forceinline__ float tanh_fast(float x)
{
    float cx = fminf(fmaxf(x, -15.f), 15.f);
    float e = __expf(2.f * cx);
    return __fdividef(e - 1.f, e + 1.f);
}

// ================== 3xBF16 GEMM template (hi/lo compensated) ================
// C[M,N] = A[M,K] @ B[N,K]^T (+bias)(+=C). M%BM==0, K%BK==0, N ragged.
template <int BM, int BN, int BK, int WM, int WN>
__global__ void __launch_bounds__(256)
mma3bf_gemm_nt(const float* __restrict__ A, const float* __restrict__ Bm,
               float* __restrict__ C, int M, int N, int K,
               const float* __restrict__ bias, int accum)
{
    constexpr int MI = WM / 16;
    constexpr int NI = WN / 8;
    constexpr int PP = BK / 2;          // pairs per row
    constexpr int KPP = PP + 4;         // padded pairs
    constexpr int F4R = BK / 4;         // float4 loads per row
    constexpr int RPP = 256 / F4R;

    __shared__ unsigned Ah[BM][KPP], Al[BM][KPP];
    __shared__ unsigned Bh[BN][KPP], Bl[BN][KPP];

    const int tid = threadIdx.x;
    const int lane = tid & 31;
    const int w = tid >> 5;
    const int warp_m = (w % (BM / WM)) * WM;
    const int warp_n = (w / (BM / WM)) * WN;
    const int m0 = blockIdx.y * BM;
    const int n0 = blockIdx.x * BN;
    const int lrow = tid / F4R;
    const int lk4 = (tid % F4R) * 4;    // float offset
    const int lp = lk4 >> 1;            // pair offset

    float acc[MI][NI][4];
#pragma unroll
    for (int i = 0; i < MI; i++)
#pragma unroll
        for (int j = 0; j < NI; j++)
#pragma unroll
            for (int q = 0; q < 4; q++) acc[i][j][q] = 0.f;

    for (int k0 = 0; k0 < K; k0 += BK) {
#pragma unroll
        for (int r = lrow; r < BM; r += RPP) {
            float4 vv = *reinterpret_cast<const float4*>(
                A + (size_t)(m0 + r) * K + k0 + lk4);
            float hx, lx, hy, ly, hz, lz, hw, lw;
            split_bf16(vv.x, hx, lx); split_bf16(vv.y, hy, ly);
            split_bf16(vv.z, hz, lz); split_bf16(vv.w, hw, lw);
            Ah[r][lp] = pack2(hx, hy); Ah[r][lp + 1] = pack2(hz, hw);
            Al[r][lp] = pack2(lx, ly); Al[r][lp + 1] = pack2(lz, lw);
        }
#pragma unroll
        for (int r = lrow; r < BN; r += RPP) {
            float4 vv = make_float4(0.f, 0.f, 0.f, 0.f);
            if (n0 + r < N)
                vv = *reinterpret_cast<const float4*>(
                    Bm + (size_t)(n0 + r) * K + k0 + lk4);
            float hx, lx, hy, ly, hz, lz, hw, lw;
            split_bf16(vv.x, hx, lx); split_bf16(vv.y, hy, ly);
            split_bf16(vv.z, hz, lz); split_bf16(vv.w, hw, lw);
            Bh[r][lp] = pack2(hx, hy); Bh[r][lp + 1] = pack2(hz, hw);
            Bl[r][lp] = pack2(lx, ly); Bl[r][lp + 1] = pack2(lz, lw);
        }
        __syncthreads();

#pragma unroll
        for (int kk = 0; kk < PP; kk += 8) {
            unsigned ah[MI][4], al[MI][4], bh[NI][2], bl[NI][2];
#pragma unroll
            for (int i = 0; i < MI; i++) {
                int r = warp_m + i * 16 + (lane >> 2);
                int cb = kk + (lane & 3);
                ah[i][0] = Ah[r][cb];     ah[i][1] = Ah[r + 8][cb];
                ah[i][2] = Ah[r][cb + 4]; ah[i][3] = Ah[r + 8][cb + 4];
                al[i][0] = Al[r][cb];     al[i][1] = Al[r + 8][cb];
                al[i][2] = Al[r][cb + 4]; al[i][3] = Al[r + 8][cb + 4];
            }
#pragma unroll
            for (int j = 0; j < NI; j++) {
                int r = warp_n + j * 8 + (lane >> 2);
                int cb = kk + (lane & 3);
                bh[j][0] = Bh[r][cb]; bh[j][1] = Bh[r][cb + 4];
                bl[j][0] = Bl[r][cb]; bl[j][1] = Bl[r][cb + 4];
            }
#pragma unroll
            for (int i = 0; i < MI; i++)
#pragma unroll
                for (int j = 0; j < NI; j++) {
                    mma_bf16(acc[i][j], ah[i], bl[j]);
                    mma_bf16(acc[i][j], al[i], bh[j]);
                    mma_bf16(acc[i][j], ah[i], bh[j]);
                }
        }
        __syncthreads();
    }

#pragma unroll
    for (int i = 0; i < MI; i++)
#pragma unroll
        for (int j = 0; j < NI; j++) {
            int row = m0 + warp_m + i * 16 + (lane >> 2);
            int col = n0 + warp_n + j * 8 + 2 * (lane & 3);
#pragma unroll
            for (int q = 0; q < 4; q++) {
                int gr = row + (q >> 1) * 8;
                int gc = col + (q & 1);
                if (gc < N) {
                    float r = acc[i][j][q];
                    if (bias) r += bias[gc];
                    size_t off = (size_t)gr * N + gc;
                    if (accum) r += C[off];
                    C[off] = r;
                }
            }
        }
}

// ============ 3xBF16 energy GEMM + fused score epilogue =====================
// T = enc[8192,1024] @ U[1024,1024]^T; epilogue: partial score
// sum_cols v * tanh(T + Ub + hW) per row, 32 deterministic slots.
// BM=128, BN=64, BK=32; warp grid 4(M)x2(N), warp tile 32x32 (MI=2, NI=4).
// Small warp tile keeps regs ~90 => 2+ CTAs/SM so load and MMA phases of
// co-resident CTAs overlap.
__global__ void __launch_bounds__(256, 2)
tgemm_score_kernel(const float* __restrict__ enc, const float* __restrict__ U,
                   const float* __restrict__ Ub, const float* __restrict__ v)
{
    constexpr int BM = 128, BN = 64, BK = 32;
    constexpr int MI = 2;               // WM=32
    constexpr int NI = 4;               // WN=32
    constexpr int PP = BK / 2;          // 16
    constexpr int KPP = PP + 4;         // 20
    constexpr int F4R = BK / 4;         // 8
    constexpr int RPP = 256 / F4R;      // 32

    __shared__ unsigned Ah[BM][KPP], Al[BM][KPP];
    __shared__ unsigned Bh[BN][KPP], Bl[BN][KPP];

    const int tid = threadIdx.x;
    const int lane = tid & 31;
    const int w = tid >> 5;
    const int lane4 = lane >> 2;
    const int lanek = lane & 3;
    const int warp_m = (w & 3) * 32;    // 4 warps along M
    const int warp_n = (w >> 2) * 32;   // 2 warps along N
    const int m0 = blockIdx.y * BM;
    const int n0 = blockIdx.x * BN;
    const int lrow = tid / F4R;
    const int lk4 = (tid % F4R) * 4;
    const int lp = lk4 >> 1;

    float acc[MI][NI][4];
#pragma unroll
    for (int i = 0; i < MI; i++)
#pragma unroll
        for (int j = 0; j < NI; j++)
#pragma unroll
            for (int q = 0; q < 4; q++) acc[i][j][q] = 0.f;

    for (int k0 = 0; k0 < Hq; k0 += BK) {
#pragma unroll
        for (int r = lrow; r < BM; r += RPP) {
            float4 vv = *reinterpret_cast<const float4*>(
                enc + (size_t)(m0 + r) * Hq + k0 + lk4);
            float hx, lx, hy, ly, hz, lz, hw, lw;
            split_bf16(vv.x, hx, lx); split_bf16(vv.y, hy, ly);
            split_bf16(vv.z, hz, lz); split_bf16(vv.w, hw, lw);
            Ah[r][lp] = pack2(hx, hy); Ah[r][lp + 1] = pack2(hz, hw);
            Al[r][lp] = pack2(lx, ly); Al[r][lp + 1] = pack2(lz, lw);
        }
#pragma unroll
        for (int r = lrow; r < BN; r += RPP) {
            float4 vv = *reinterpret_cast<const float4*>(
                U + (size_t)(n0 + r) * Hq + k0 + lk4);
            float hx, lx, hy, ly, hz, lz, hw, lw;
            split_bf16(vv.x, hx, lx); split_bf16(vv.y, hy, ly);
            split_bf16(vv.z, hz, lz); split_bf16(vv.w, hw, lw);
            Bh[r][lp] = pack2(hx, hy); Bh[r][lp + 1] = pack2(hz, hw);
            Bl[r][lp] = pack2(lx, ly); Bl[r][lp + 1] = pack2(lz, lw);
        }
        __syncthreads();

#pragma unroll
        for (int kk = 0; kk < PP; kk += 8) {
            unsigned ah[MI][4], al[MI][4], bh[NI][2], bl[NI][2];
#pragma unroll
            for (int i = 0; i < MI; i++) {
                int r = warp_m + i * 16 + lane4;
                int cb = kk + lanek;
                ah[i][0] = Ah[r][cb];     ah[i][1] = Ah[r + 8][cb];
                ah[i][2] = Ah[r][cb + 4]; ah[i][3] = Ah[r + 8][cb + 4];
                al[i][0] = Al[r][cb];     al[i][1] = Al[r + 8][cb];
                al[i][2] = Al[r][cb + 4]; al[i][3] = Al[r + 8][cb + 4];
            }
#pragma unroll
            for (int j = 0; j < NI; j++) {
                int r = warp_n + j * 8 + lane4;
                int cb = kk + lanek;
                bh[j][0] = Bh[r][cb]; bh[j][1] = Bh[r][cb + 4];
                bl[j][0] = Bl[r][cb]; bl[j][1] = Bl[r][cb + 4];
            }
#pragma unroll
            for (int i = 0; i < MI; i++)
#pragma unroll
                for (int j = 0; j < NI; j++) {
                    mma_bf16(acc[i][j], ah[i], bl[j]);
                    mma_bf16(acc[i][j], al[i], bh[j]);
                    mma_bf16(acc[i][j], ah[i], bh[j]);
                }
        }
        __syncthreads();
    }

    // ---- fused score epilogue over this warp's 32 columns ------------------
    float vv[NI][2], uu[NI][2];
#pragma unroll
    for (int j = 0; j < NI; j++)
#pragma unroll
        for (int qc = 0; qc < 2; qc++) {
            int c = n0 + warp_n + j * 8 + 2 * lanek + qc;
            vv[j][qc] = v[c];
            uu[j][qc] = Ub[c];
        }

    const int slot = blockIdx.x * 2 + (w >> 2);   // 16 blocks x 2 n-warps = 32
#pragma unroll
    for (int i = 0; i < MI; i++)
#pragma unroll
        for (int qr = 0; qr < 2; qr++) {
            int row = m0 + warp_m + i * 16 + lane4 + qr * 8;
            int b = row & (Bq - 1);
            const float* hwr = g_hW + (size_t)b * Hq + n0 + warp_n + 2 * lanek;
            float part = 0.f;
#pragma unroll
            for (int j = 0; j < NI; j++)
#pragma unroll
                for (int qc = 0; qc < 2; qc++) {
                    float t = acc[i][j][2 * qr + qc] + uu[j][qc]
                              + hwr[j * 8 + qc];
                    part += vv[j][qc] * tanh_fast(t);
                }
            part += __shfl_xor_sync(0xffffffffu, part, 1);
            part += __shfl_xor_sync(0xffffffffu, part, 2);
            if (lanek == 0)
                g_spart[(size_t)slot * SBq + row] = part;
        }
}

// ================== single-pass tf32 GEMM (logits) ==========================
template <int BM, int BN, int BK, int WM, int WN>
__global__ void __launch_bounds__(256)
mma_gemm_nt(const float* __restrict__ A, const float* __restrict__ Bm,
            float* __restrict__ C, int M, int N, int K,
            const float* __restrict__ bias)
{
    constexpr int MI = WM / 16;
    constexpr int NI = WN / 8;
    constexpr int KP = BK + 4;
    constexpr int F4R = BK / 4;
    constexpr int RPP = 256 / F4R;

    __shared__ unsigned As[BM][KP];
    __shared__ unsigned Bs[BN][KP];

    const int tid = threadIdx.x;
    const int lane = tid & 31;
    const int w = tid >> 5;
    const int warp_m = (w % (BM / WM)) * WM;
    const int warp_n = (w / (BM / WM)) * WN;
    const int m0 = blockIdx.y * BM;
    const int n0 = blockIdx.x * BN;
    const int lrow = tid / F4R;
    const int lk4 = (tid % F4R) * 4;

    float acc[MI][NI][4];
#pragma unroll
    for (int i = 0; i < MI; i++)
#pragma unroll
        for (int j = 0; j < NI; j++)
#pragma unroll
            for (int q = 0; q < 4; q++) acc[i][j][q] = 0.f;

    for (int k0 = 0; k0 < K; k0 += BK) {
#pragma unroll
        for (int r = lrow; r < BM; r += RPP) {
            float4 vv = *reinterpret_cast<const float4*>(
                A + (size_t)(m0 + r) * K + k0 + lk4);
            uint4 u;
            u.x = f2tf32(vv.x); u.y = f2tf32(vv.y);
            u.z = f2tf32(vv.z); u.w = f2tf32(vv.w);
            *reinterpret_cast<uint4*>(&As[r][lk4]) = u;
        }
#pragma unroll
        for (int r = lrow; r < BN; r += RPP) {
            float4 vv = make_float4(0.f, 0.f, 0.f, 0.f);
            if (n0 + r < N)
                vv = *reinterpret_cast<const float4*>(
                    Bm + (size_t)(n0 + r) * K + k0 + lk4);
            uint4 u;
            u.x = f2tf32(vv.x); u.y = f2tf32(vv.y);
            u.z = f2tf32(vv.z); u.w = f2tf32(vv.w);
            *reinterpret_cast<uint4*>(&Bs[r][lk4]) = u;
        }
        __syncthreads();

#pragma unroll
        for (int kk = 0; kk < BK; kk += 8) {
            unsigned af[MI][4], bf[NI][2];
#pragma unroll
            for (int i = 0; i < MI; i++) {
                int r = warp_m + i * 16 + (lane >> 2);
                int cb = kk + (lane & 3);
                af[i][0] = As[r][cb];     af[i][1] = As[r + 8][cb];
                af[i][2] = As[r][cb + 4]; af[i][3] = As[r + 8][cb + 4];
            }
#pragma unroll
            for (int j = 0; j < NI; j++) {
                int r = warp_n + j * 8 + (lane >> 2);
                int cb = kk + (lane & 3);
                bf[j][0] = Bs[r][cb]; bf[j][1] = Bs[r][cb + 4];
            }
#pragma unroll
            for (int i = 0; i < MI; i++)
#pragma unroll
                for (int j = 0; j < NI; j++)
                    mma_tf32(acc[i][j], af[i], bf[j]);
        }
        __syncthreads();
    }

#pragma unroll
    for (int i = 0; i < MI; i++)
#pragma unroll
        for (int j = 0; j < NI; j++) {
            int row = m0 + warp_m + i * 16 + (lane >> 2);
            int col = n0 + warp_n + j * 8 + 2 * (lane & 3);
#pragma unroll
            for (int q = 0; q < 4; q++) {
                int gr = row + (q >> 1) * 8;
                int gc = col + (q & 1);
                if (gc < N) {
                    float r = acc[i][j][q];
                    if (bias) r += bias[gc];
                    C[(size_t)gr * N + gc] = r;
                }
            }
        }
}

// ---------------- pointwise / reduction kernels -----------------------------
__global__ void softmax_kernel(float* __restrict__ attn_out)
{
    __shared__ float sm[Sq];
    int b = blockIdx.x, t = threadIdx.x;
    float x = 0.f;
#pragma unroll
    for (int q = 0; q < NSLOT; q++)
        x += g_spart[(size_t)q * SBq + t * Bq + b];
    sm[t] = x; __syncthreads();
    for (int o = 64; o > 0; o >>= 1) {
        if (t < o) sm[t] = fmaxf(sm[t], sm[t + o]);
        __syncthreads();
    }
    float m = sm[0];
    __syncthreads();
    float e = expf(x - m);
    sm[t] = e; __syncthreads();
    for (int o = 64; o > 0; o >>= 1) {
        if (t < o) sm[t] += sm[t + o];
        __syncthreads();
    }
    attn_out[b * Sq + t] = e / sm[0];
}

__global__ void context_kernel(const float* __restrict__ attn,
                               const float* __restrict__ enc)
{
    __shared__ float aw[Sq];
    int idx = blockIdx.x * 256 + threadIdx.x;
    int b = idx >> 10;
    int h = idx & (Hq - 1);
    if (threadIdx.x < Sq) aw[threadIdx.x] = attn[b * Sq + threadIdx.x];
    __syncthreads();
    float acc = 0.f;
#pragma unroll 4
    for (int s = 0; s < Sq; s++)
        acc = fmaf(aw[s], enc[((size_t)s * Bq + b) * Hq + h], acc);
    g_ctx[idx] = acc;
}

__global__ void xbuild_kernel(const int* __restrict__ seq,
                              const float* __restrict__ emb)
{
    int idx = blockIdx.x * 256 + threadIdx.x;
    int b = idx / KIq;
    int j = idx - b * KIq;
    float val;
    if (j < Eq) val = emb[(size_t)seq[b] * Eq + j];
    else        val = g_ctx[b * Hq + (j - Eq)];
    g_x[idx] = val;
}

__device__ __forceinline__ float sigf(float x) { return 1.f / (1.f + expf(-x)); }

__global__ void lstm_kernel(const float* __restrict__ c0,
                            float* __restrict__ h_new,
                            float* __restrict__ c_new)
{
    int idx = blockIdx.x * 256 + threadIdx.x;
    int b = idx >> 10;
    int h = idx & (Hq - 1);
    const float* g = g_gates + ((size_t)b << 12);
    float vi = g[h];
    float vf = g[Hq + h];
    float vg = g[2 * Hq + h];
    float vo = g[3 * Hq + h];
    float c = sigf(vf) * c0[idx] + sigf(vi) * tanhf(vg);
    c_new[idx] = c;
    h_new[idx] = sigf(vo) * tanhf(c);
}

__device__ __forceinline__ float blk_red_max(float v, float* red)
{
    int t = threadIdx.x;
#pragma unroll
    for (int o = 16; o > 0; o >>= 1) v = fmaxf(v, __shfl_xor_sync(~0u, v, o));
    if ((t & 31) == 0) red[t >> 5] = v;
    __syncthreads();
    if (t < 32) {
        v = red[t];
#pragma unroll
        for (int o = 16; o > 0; o >>= 1) v = fmaxf(v, __shfl_xor_sync(~0u, v, o));
        if (t == 0) red[0] = v;
    }
    __syncthreads();
    float r = red[0];
    __syncthreads();
    return r;
}

__device__ __forceinline__ float blk_red_sum(float v, float* red)
{
    int t = threadIdx.x;
#pragma unroll
    for (int o = 16; o > 0; o >>= 1) v += __shfl_xor_sync(~0u, v, o);
    if ((t & 31) == 0) red[t >> 5] = v;
    __syncthreads();
    if (t < 32) {
        v = red[t];
#pragma unroll
        for (int o = 16; o > 0; o >>= 1) v += __shfl_xor_sync(~0u, v, o);
        if (t == 0) red[0] = v;
    }
    __syncthreads();
    float r = red[0];
    __syncthreads();
    return r;
}

__global__ void logsoftmax_kernel(float* __restrict__ out)
{
    __shared__ float red[32];
    int b = blockIdx.x;
    float* row = out + (size_t)b * Vq;
    int t = threadIdx.x;

    float m = -1e30f;
    for (int j = t; j < Vq; j += 1024) m = fmaxf(m, row[j]);
    m = blk_red_max(m, red);

    float s = 0.f;
    for (int j = t; j < Vq; j += 1024) s += expf(row[j] - m);
    s = blk_red_sum(s, red);

    float lse = m + logf(s);
    for (int j = t; j < Vq; j += 1024) row[j] -= lse;
}

// ---------------------------------------------------------------------------
extern "C" void kernel_launch(void* const* d_in, const int* in_sizes, int n_in,
                              void* d_out, int out_size)
{
    const int*   seq     = (const int*)d_in[0];
    const float* h0      = (const float*)d_in[1];
    const float* c0      = (const float*)d_in[2];
    const float* enc     = (const float*)d_in[3];
    const float* emb     = (const float*)d_in[4];
    const float* W_ih    = (const float*)d_in[5];
    const float* W_hh    = (const float*)d_in[6];
    const float* b_ih    = (const float*)d_in[7];
    const float* b_hh    = (const float*)d_in[8];
    const float* attn_W  = (const float*)d_in[9];
    const float* attn_Wb = (const float*)d_in[10];
    const float* attn_U  = (const float*)d_in[11];
    const float* attn_Ub = (const float*)d_in[12];
    const float* attn_v  = (const float*)d_in[13];
    const float* out_W   = (const float*)d_in[14];
    const float* out_b   = (const float*)d_in[15];

    float* out      = (float*)d_out;
    float* o_logits = out;                          // [B, V]
    float* o_h      = out + (size_t)Bq * Vq;        // [1, B, H]
    float* o_c      = o_h + Bq * Hq;                // [1, B, H]
    float* o_attn   = o_c + Bq * Hq;                // [B, 1, S]

    float *hW, *x, *gates;
    cudaGetSymbolAddress((void**)&hW,    g_hW);
    cudaGetSymbolAddress((void**)&x,     g_x);
    cudaGetSymbolAddress((void**)&gates, g_gates);

    // 1) hW = h0 @ attn_W^T + attn_Wb            [64, 1024]   (3xBF16)
    mma3bf_gemm_nt<64, 128, 32, 32, 32><<<dim3(Hq / 128, 1), 256>>>(
        h0, attn_W, hW, Bq, Hq, Hq, attn_Wb, 0);

    // 2) fused energy GEMM (3xBF16, BN=64 re-tile) + score partials
    tgemm_score_kernel<<<dim3(Hq / 64, SBq / 128), 256>>>(
        enc, attn_U, attn_Ub, attn_v);

    // 3) attn = softmax(reduce(spart)) -> output region
    softmax_kernel<<<Bq, Sq>>>(o_attn);

    // 4) context = attn @ enc                    [64, 1024]
    context_kernel<<<Bq * Hq / 256, 256>>>(o_attn, enc);

    // 5) x = [emb[seq] ; context]                [64, 1536]
    xbuild_kernel<<<Bq * KIq / 256, 256>>>(seq, emb);

    // 6) gates  = x @ W_ih^T + b_ih              [64, 4096]   (3xBF16)
    mma3bf_gemm_nt<64, 128, 32, 32, 32><<<dim3(G4q / 128, 1), 256>>>(
        x, W_ih, gates, Bq, G4q, KIq, b_ih, 0);

    // 7) gates += h0 @ W_hh^T + b_hh                          (3xBF16)
    mma3bf_gemm_nt<64, 128, 32, 32, 32><<<dim3(G4q / 128, 1), 256>>>(
        h0, W_hh, gates, Bq, G4q, Hq, b_hh, 1);

    // 8) LSTM pointwise -> h_new, c_new in output
    lstm_kernel<<<Bq * Hq / 256, 256>>>(c0, o_h, o_c);

    // 9) logits = h_new @ out_W^T + out_b        [64, 50257]  (single tf32)
    mma_gemm_nt<64, 128, 32, 32, 32><<<dim3((Vq + 127) / 128, 1), 256>>>(
        o_h, out_W, o_logits, Bq, Vq, Hq, out_b);

    // 10) in-place log_softmax over V
    logsoftmax_kernel<<<Bq, 1024>>>(o_logits);
}